// round 9
// baseline (speedup 1.0000x reference)
#include <cuda_runtime.h>
#include <math.h>
#include <stdint.h>

// Problem constants
#define S_LEN   2048
#define HIDDEN  2048
#define NH      16
#define HD      128
#define RD      64
#define KVC     512
#define QCDIM   1024
#define DQK     192   // HD + RD

// ---------------------------------------------------------------------------
// Scratch buffers
// ---------------------------------------------------------------------------
__device__ float g_dq [S_LEN * (KVC + QCDIM)];        // tf32 bits
__device__ float g_kvu[S_LEN * (2*NH*HD + NH*RD)];    // tf32 bits
__device__ float g_qu [S_LEN * (NH*HD + NH*RD)];      // tf32 bits
__device__ float g_Kb [S_LEN * NH * DQK];             // tf32 bits
__device__ float g_Qb [S_LEN * NH * DQK];             // tf32 bits (scaled)
__device__ float g_VT [NH * HD * S_LEN];              // tf32 bits
__device__ float g_ctx[S_LEN * NH * HD];              // tf32 bits
__device__ float2 g_trig[NH * 32];
// converted (tf32-bit) copies of x + all weights
#define WCV_TOTAL 17301504
__device__ float g_wcv[WCV_TOTAL];

// ---------------------------------------------------------------------------
// Helpers
// ---------------------------------------------------------------------------
__device__ __forceinline__ uint32_t smem_u32(const void* p) {
    uint32_t a;
    asm("{ .reg .u64 t; cvta.to.shared.u64 t, %1; cvt.u32.u64 %0, t; }"
        : "=r"(a) : "l"(p));
    return a;
}
__device__ __forceinline__ uint32_t f2tf32(float v) {
    uint32_t u;
    asm("cvt.rna.tf32.f32 %0, %1;" : "=r"(u) : "f"(v));
    return u;
}
#define CP_ASYNC16(dst, src) \
    asm volatile("cp.async.cg.shared.global [%0], [%1], 16;" :: "r"(dst), "l"(src) : "memory")
#define CP_COMMIT() asm volatile("cp.async.commit_group;" ::: "memory")
#define CP_WAIT0()  asm volatile("cp.async.wait_group 0;" ::: "memory")
#define CP_WAIT1()  asm volatile("cp.async.wait_group 1;" ::: "memory")
#define CP_WAIT2()  asm volatile("cp.async.wait_group 2;" ::: "memory")

__device__ __forceinline__ void mma_tf32(float* c, const uint32_t* a, const uint32_t* b) {
    asm volatile(
        "mma.sync.aligned.m16n8k8.row.col.f32.tf32.tf32.f32 "
        "{%0,%1,%2,%3}, {%4,%5,%6,%7}, {%8,%9}, {%0,%1,%2,%3};"
        : "+f"(c[0]), "+f"(c[1]), "+f"(c[2]), "+f"(c[3])
        : "r"(a[0]), "r"(a[1]), "r"(a[2]), "r"(a[3]), "r"(b[0]), "r"(b[1]));
}

// ---------------------------------------------------------------------------
// Elementwise fp32 -> tf32-bit conversion (float4 vectorized)
// ---------------------------------------------------------------------------
__global__ void cvt_tf32_kernel(const float4* __restrict__ in,
                                float4* __restrict__ out, int n4)
{
    const int i = blockIdx.x * blockDim.x + threadIdx.x;
    if (i >= n4) return;
    float4 v = in[i];
    v.x = __uint_as_float(f2tf32(v.x));
    v.y = __uint_as_float(f2tf32(v.y));
    v.z = __uint_as_float(f2tf32(v.z));
    v.w = __uint_as_float(f2tf32(v.w));
    out[i] = v;
}

// ---------------------------------------------------------------------------
// Segmented-B tensor-core NT GEMM. Operands are PRE-CONVERTED tf32 bits.
// cvt_out != 0 -> epilogue stores tf32 bits; else fp32.
// ---------------------------------------------------------------------------
#define KT        32
#define RS        36
#define TILE_F    (128 * RS)
#define STAGE_F   (2 * TILE_F)
#define SMEM_BYTES (3 * STAGE_F * 4)      // 110592

__device__ __forceinline__ void load_tile(
    const float* __restrict__ A, const float* __restrict__ B,
    int mBase, int nLoc, int lda, int ldb, int k0,
    uint32_t dstA, uint32_t dstB, int tid)
{
    #pragma unroll
    for (int i = 0; i < 4; ++i) {
        const int idx = i * 256 + tid;
        const int row = idx >> 3;
        const int seg = idx & 7;
        const uint32_t off = (uint32_t)(row * (RS * 4) + seg * 16);
        CP_ASYNC16(dstA + off, A + (long long)(mBase + row) * lda + k0 + seg * 4);
        CP_ASYNC16(dstB + off, B + (long long)(nLoc + row) * ldb + k0 + seg * 4);
    }
}

__global__ void __launch_bounds__(256, 2) mma_nt_kernel(
    const float* __restrict__ A,
    const float* __restrict__ B0, const float* __restrict__ B1,
    const float* __restrict__ B2,
    const float* __restrict__ bias0, const float* __restrict__ bias1,
    const float* __restrict__ bias2,
    int n1, int n2,
    float* __restrict__ C,
    int K, int lda, int ldc, int cvt_out)
{
    extern __shared__ float smem[];
    const uint32_t sb = smem_u32(smem);
    const int tid = threadIdx.x;
    const int wid = tid >> 5;
    const int lane = tid & 31;
    const int g = lane >> 2;
    const int t = lane & 3;
    const int warp_m = wid >> 1;
    const int warp_n = wid & 1;

    const int mBase = blockIdx.y * 128;
    const int nBase = blockIdx.x * 128;

    const float* B; const float* bp; int nLoc;
    if (nBase >= n2)      { B = B2; bp = bias2; nLoc = nBase - n2; }
    else if (nBase >= n1) { B = B1; bp = bias1; nLoc = nBase - n1; }
    else                  { B = B0; bp = bias0; nLoc = nBase; }
    const int ldb = K;

    float acc[2][8][4];
    #pragma unroll
    for (int i = 0; i < 2; ++i)
        #pragma unroll
        for (int j = 0; j < 8; ++j)
            #pragma unroll
            for (int q = 0; q < 4; ++q) acc[i][j][q] = 0.f;

    const int T = K / KT;
    #pragma unroll
    for (int s = 0; s < 3; ++s) {
        load_tile(A, B, mBase, nLoc, lda, ldb, s * KT,
                  sb + s * (STAGE_F * 4),
                  sb + s * (STAGE_F * 4) + TILE_F * 4, tid);
        CP_COMMIT();
    }

    for (int kt = 0; kt < T; ++kt) {
        const int b = kt - (kt / 3) * 3;
        CP_WAIT2();
        __syncthreads();

        const float* As = smem + b * STAGE_F;
        const float* Bs = As + TILE_F;

        #pragma unroll
        for (int ks = 0; ks < 4; ++ks) {
            const int kc = ks * 8 + t;
            uint32_t af[2][4];
            #pragma unroll
            for (int mt = 0; mt < 2; ++mt) {
                const float* ap = As + (warp_m * 32 + mt * 16 + g) * RS + kc;
                af[mt][0] = __float_as_uint(ap[0]);
                af[mt][1] = __float_as_uint(ap[8 * RS]);
                af[mt][2] = __float_as_uint(ap[4]);
                af[mt][3] = __float_as_uint(ap[8 * RS + 4]);
            }
            uint32_t bf[8][2];
            #pragma unroll
            for (int nt = 0; nt < 8; ++nt) {
                const float* bpr = Bs + (warp_n * 64 + nt * 8 + g) * RS + kc;
                bf[nt][0] = __float_as_uint(bpr[0]);
                bf[nt][1] = __float_as_uint(bpr[4]);
            }
            #pragma unroll
            for (int mt = 0; mt < 2; ++mt)
                #pragma unroll
                for (int nt = 0; nt < 8; ++nt)
                    mma_tf32(acc[mt][nt], af[mt], bf[nt]);
        }

        __syncthreads();
        if (kt + 3 < T) {
            load_tile(A, B, mBase, nLoc, lda, ldb, (kt + 3) * KT,
                      sb + b * (STAGE_F * 4),
                      sb + b * (STAGE_F * 4) + TILE_F * 4, tid);
        }
        CP_COMMIT();
    }

    #pragma unroll
    for (int mt = 0; mt < 2; ++mt) {
        const long long row0 = mBase + warp_m * 32 + mt * 16 + g;
        #pragma unroll
        for (int nt = 0; nt < 8; ++nt) {
            const int colLoc = warp_n * 64 + nt * 8 + 2 * t;
            const int col = nBase + colLoc;
            float2 lo, hi;
            const float b0 = bp[nLoc + colLoc], b1 = bp[nLoc + colLoc + 1];
            lo.x = acc[mt][nt][0] + b0;
            lo.y = acc[mt][nt][1] + b1;
            hi.x = acc[mt][nt][2] + b0;
            hi.y = acc[mt][nt][3] + b1;
            if (cvt_out) {
                lo.x = __uint_as_float(f2tf32(lo.x));
                lo.y = __uint_as_float(f2tf32(lo.y));
                hi.x = __uint_as_float(f2tf32(hi.x));
                hi.y = __uint_as_float(f2tf32(hi.y));
            }
            *(float2*)(C + row0 * (long long)ldc + col)       = lo;
            *(float2*)(C + (row0 + 8) * (long long)ldc + col) = hi;
        }
    }
}

// ---------------------------------------------------------------------------
// Fused flash attention, 512 threads (16 warps), k-split warp pairs.
//   warp_m = wid>>1 owns 16 q-rows; warp_n = wid&1 owns 64 of 128 k-tokens.
// ---------------------------------------------------------------------------
#define RSQ 196
#define RSK 36
#define RSV 132
#define QS_F (128 * RSQ)            // 25088
#define KS_F (128 * RSK)            // 4608 per buffer (3 buffers)
#define VS_F (128 * RSV)            // 16896
#define OFFK0 QS_F
#define OFFK1 (QS_F + KS_F)
#define OFFK2 (QS_F + 2 * KS_F)
#define OFFV  (QS_F + 3 * KS_F)
#define OFFC  (QS_F + 3 * KS_F + VS_F)
#define FL_SMEM_BYTES ((OFFC + 512) * 4)   // 225280

__device__ __forceinline__ void fl_load_k512(uint32_t dstB, const float* __restrict__ Kb,
                                             int h, int kBase, int c, int tid) {
    #pragma unroll
    for (int i = 0; i < 2; ++i) {
        const int idx = i * 512 + tid;
        const int r = idx >> 3;
        const int seg = idx & 7;
        CP_ASYNC16(dstB + (uint32_t)(r * (RSK * 4) + seg * 16),
                   Kb + (long long)(kBase + r) * (NH * DQK) + h * DQK + c * 32 + seg * 4);
    }
}
__device__ __forceinline__ void fl_load_v512(uint32_t dstB, const float* __restrict__ VTp,
                                             int h, int kBase, int tid) {
    #pragma unroll
    for (int i = 0; i < 8; ++i) {
        const int idx = i * 512 + tid;
        const int r = idx >> 5;
        const int seg = idx & 31;
        CP_ASYNC16(dstB + (uint32_t)(r * (RSV * 4) + seg * 16),
                   VTp + (long long)(h * HD + r) * S_LEN + kBase + seg * 4);
    }
}

__global__ void __launch_bounds__(512) flash_kernel(
    const float* __restrict__ Qb, const float* __restrict__ Kb,
    const float* __restrict__ VTp, float* __restrict__ ctx)
{
    extern __shared__ float fsm[];
    const uint32_t sb = smem_u32(fsm);
    const int tid = threadIdx.x;
    const int wid = tid >> 5;
    const int lane = tid & 31;
    const int g = lane >> 2;
    const int t = lane & 3;
    const int warp_m = wid >> 1;     // 0..7
    const int warp_n = wid & 1;      // 0..1
    const int qBase = blockIdx.x * 128;
    const int h = blockIdx.y;
    const int row = warp_m * 16 + g;

    const uint32_t kBufAddr[3] = { sb + OFFK0 * 4, sb + OFFK1 * 4, sb + OFFK2 * 4 };
    const int      kBufOff[3]  = { OFFK0, OFFK1, OFFK2 };
    float* cmax = fsm + OFFC;
    float* csum = fsm + OFFC + 256;

    float Sacc[8][4];
    float Oacc[16][4];
    #pragma unroll
    for (int nt = 0; nt < 16; ++nt)
        #pragma unroll
        for (int i = 0; i < 4; ++i) Oacc[nt][i] = 0.f;
    float m0 = -INFINITY, m1 = -INFINITY, l0 = 0.f, l1 = 0.f;

    // Prologue: Q (group 1), K(0,0) (group 2), K(0,1) (group 3)
    #pragma unroll
    for (int i = 0; i < 12; ++i) {
        const int idx = i * 512 + tid;        // 6144 slots = 128 rows x 48 segs
        const int r = idx / 48;
        const int seg = idx % 48;
        CP_ASYNC16(sb + (uint32_t)(r * (RSQ * 4) + seg * 16),
                   Qb + (long long)(qBase + r) * (NH * DQK) + h * DQK + seg * 4);
    }
    CP_COMMIT();
    fl_load_k512(kBufAddr[0], Kb, h, 0, 0, tid);
    CP_COMMIT();
    fl_load_k512(kBufAddr[1], Kb, h, 0, 1, tid);
    CP_COMMIT();

    for (int j = 0; j < 16; ++j) {
        const int kBase = j * 128;
        #pragma unroll
        for (int nt = 0; nt < 8; ++nt)
            #pragma unroll
            for (int i = 0; i < 4; ++i) Sacc[nt][i] = 0.f;

        #pragma unroll
        for (int c = 0; c < 6; ++c) {
            if (c == 5 && j == 15) { CP_WAIT0(); } else { CP_WAIT1(); }
            __syncthreads();
            if (c == 0) {
                fl_load_k512(kBufAddr[2], Kb, h, kBase, 2, tid);
                fl_load_v512(sb + OFFV * 4, VTp, h, kBase, tid);
                CP_COMMIT();
            } else if (c <= 3) {
                fl_load_k512(kBufAddr[(c + 2) % 3], Kb, h, kBase, c + 2, tid);
                CP_COMMIT();
            } else if (j < 15) {
                fl_load_k512(kBufAddr[c - 4], Kb, h, kBase + 128, c - 4, tid);
                CP_COMMIT();
            }

            const int kOffBase = kBufOff[c % 3] + warp_n * 64 * RSK;
            #pragma unroll
            for (int s = 0; s < 4; ++s) {
                const float* ap = fsm + row * RSQ + c * 32 + s * 8 + t;
                uint32_t a[4];
                a[0] = __float_as_uint(ap[0]);
                a[1] = __float_as_uint(ap[8 * RSQ]);
                a[2] = __float_as_uint(ap[4]);
                a[3] = __float_as_uint(ap[8 * RSQ + 4]);
                const float* bb = fsm + kOffBase + g * RSK + s * 8 + t;
                #pragma unroll
                for (int nt = 0; nt < 8; ++nt) {
                    uint32_t b[2];
                    b[0] = __float_as_uint(bb[nt * 8 * RSK]);
                    b[1] = __float_as_uint(bb[nt * 8 * RSK + 4]);
                    mma_tf32(Sacc[nt], a, b);
                }
            }
        }

        // --- online softmax, merged across warp_n pair ---
        float bm0 = -INFINITY, bm1 = -INFINITY;
        #pragma unroll
        for (int nt = 0; nt < 8; ++nt) {
            bm0 = fmaxf(bm0, fmaxf(Sacc[nt][0], Sacc[nt][1]));
            bm1 = fmaxf(bm1, fmaxf(Sacc[nt][2], Sacc[nt][3]));
        }
        bm0 = fmaxf(bm0, __shfl_xor_sync(0xffffffffu, bm0, 1));
        bm0 = fmaxf(bm0, __shfl_xor_sync(0xffffffffu, bm0, 2));
        bm1 = fmaxf(bm1, __shfl_xor_sync(0xffffffffu, bm1, 1));
        bm1 = fmaxf(bm1, __shfl_xor_sync(0xffffffffu, bm1, 2));
        if (t == 0) {
            cmax[warp_n * 128 + row]     = bm0;
            cmax[warp_n * 128 + row + 8] = bm1;
        }
        __syncthreads();
        const float obm0 = cmax[(1 - warp_n) * 128 + row];
        const float obm1 = cmax[(1 - warp_n) * 128 + row + 8];
        const float mn0 = fmaxf(m0, fmaxf(bm0, obm0));
        const float mn1 = fmaxf(m1, fmaxf(bm1, obm1));
        const float f0 = __expf(m0 - mn0), f1 = __expf(m1 - mn1);
        m0 = mn0; m1 = mn1;
        float s0 = 0.f, s1 = 0.f;
        #pragma unroll
        for (int nt = 0; nt < 8; ++nt) {
            float p0 = __expf(Sacc[nt][0] - mn0);
            float p1 = __expf(Sacc[nt][1] - mn0);
            float p2 = __expf(Sacc[nt][2] - mn1);
            float p3 = __expf(Sacc[nt][3] - mn1);
            s0 += p0 + p1;
            s1 += p2 + p3;
            Sacc[nt][0] = __uint_as_float(f2tf32(p0));
            Sacc[nt][1] = __uint_as_float(f2tf32(p1));
            Sacc[nt][2] = __uint_as_float(f2tf32(p2));
            Sacc[nt][3] = __uint_as_float(f2tf32(p3));
        }
        s0 += __shfl_xor_sync(0xffffffffu, s0, 1);
        s0 += __shfl_xor_sync(0xffffffffu, s0, 2);
        s1 += __shfl_xor_sync(0xffffffffu, s1, 1);
        s1 += __shfl_xor_sync(0xffffffffu, s1, 2);
        if (t == 0) {
            csum[warp_n * 128 + row]     = s0;
            csum[warp_n * 128 + row + 8] = s1;
        }
        __syncthreads();
        const float os0 = csum[(1 - warp_n) * 128 + row];
        const float os1 = csum[(1 - warp_n) * 128 + row + 8];
        l0 = l0 * f0 + s0 + os0;
        l1 = l1 * f1 + s1 + os1;
        #pragma unroll
        for (int nt = 0; nt < 16; ++nt) {
            Oacc[nt][0] *= f0; Oacc[nt][1] *= f0;
            Oacc[nt][2] *= f1; Oacc[nt][3] *= f1;
        }

        // --- O(partial, this warp's 64 tokens) += P @ V ---
        const int srcA = (lane & ~3) | (t >> 1);
        const int srcB = srcA + 2;
        #pragma unroll
        for (int kc = 0; kc < 8; ++kc) {
            const float v00 = __shfl_sync(0xffffffffu, Sacc[kc][0], srcA);
            const float v01 = __shfl_sync(0xffffffffu, Sacc[kc][1], srcA);
            const float v10 = __shfl_sync(0xffffffffu, Sacc[kc][0], srcB);
            const float v11 = __shfl_sync(0xffffffffu, Sacc[kc][1], srcB);
            const float w00 = __shfl_sync(0xffffffffu, Sacc[kc][2], srcA);
            const float w01 = __shfl_sync(0xffffffffu, Sacc[kc][3], srcA);
            const float w10 = __shfl_sync(0xffffffffu, Sacc[kc][2], srcB);
            const float w11 = __shfl_sync(0xffffffffu, Sacc[kc][3], srcB);
            uint32_t a[4];
            a[0] = __float_as_uint((t & 1) ? v01 : v00);
            a[1] = __float_as_uint((t & 1) ? w01 : w00);
            a[2] = __float_as_uint((t & 1) ? v11 : v10);
            a[3] = __float_as_uint((t & 1) ? w11 : w10);
            const float* vb = fsm + OFFV + g * RSV + warp_n * 64 + kc * 8 + t;
            #pragma unroll
            for (int nt = 0; nt < 16; ++nt) {
                uint32_t b[2];
                b[0] = __float_as_uint(vb[nt * 8 * RSV]);
                b[1] = __float_as_uint(vb[nt * 8 * RSV + 4]);
                mma_tf32(Oacc[nt], a, b);
            }
        }
    }

    // --- Epilogue: merge warp_n partial O via smem (reuse Q area), write ctx ---
    __syncthreads();
    if (warp_n == 1) {
        #pragma unroll
        for (int nt = 0; nt < 16; ++nt) {
            const int col = nt * 8 + 2 * t;
            fsm[row * 128 + col]           = Oacc[nt][0];
            fsm[row * 128 + col + 1]       = Oacc[nt][1];
            fsm[(row + 8) * 128 + col]     = Oacc[nt][2];
            fsm[(row + 8) * 128 + col + 1] = Oacc[nt][3];
        }
    }
    __syncthreads();
    if (warp_n == 0) {
        const float il0 = 1.f / l0, il1 = 1.f / l1;
        const long long q0 = qBase + row;
        #pragma unroll
        for (int nt = 0; nt < 16; ++nt) {
            const int col = nt * 8 + 2 * t;
            float2 lo, hi;
            lo.x = (Oacc[nt][0] + fsm[row * 128 + col])           * il0;
            lo.y = (Oacc[nt][1] + fsm[row * 128 + col + 1])       * il0;
            hi.x = (Oacc[nt][2] + fsm[(row + 8) * 128 + col])     * il1;
            hi.y = (Oacc[nt][3] + fsm[(row + 8) * 128 + col + 1]) * il1;
            lo.x = __uint_as_float(f2tf32(lo.x));
            lo.y = __uint_as_float(f2tf32(lo.y));
            hi.x = __uint_as_float(f2tf32(hi.x));
            hi.y = __uint_as_float(f2tf32(hi.y));
            *(float2*)(ctx + q0 * (NH * HD) + h * HD + col)       = lo;
            *(float2*)(ctx + (q0 + 8) * (NH * HD) + h * HD + col) = hi;
        }
    }
}

// ---------------------------------------------------------------------------
// Trig table init
// ---------------------------------------------------------------------------
__global__ void trig_init_kernel()
{
    const int idx = threadIdx.x;   // 512 threads
    const int h = idx >> 5;
    const int j = idx & 31;
    const float inv_freq = powf(10000.f, -(2.f * j) / (float)RD);
    const float ang = (float)h * inv_freq;
    g_trig[idx] = make_float2(cosf(ang), sinf(ang));
}

// ---------------------------------------------------------------------------
// Assemble concat [s, h, 192], rope via table, output tf32(val * mult)
// ---------------------------------------------------------------------------
__global__ void assemble_rope_kernel(const float* __restrict__ comp, int comp_ld,
                                     const float* __restrict__ rope, int rope_ld,
                                     float* __restrict__ out, float mult)
{
    const int idx = blockIdx.x * blockDim.x + threadIdx.x;
    if (idx >= S_LEN * NH * DQK) return;
    const int s = idx / (NH * DQK);
    const int c = idx - s * (NH * DQK);
    const int h = c / DQK;
    const int d = c - h * DQK;
    float val;
    if (d < HD) {
        val = comp[(long long)s * comp_ld + h * HD + d];
    } else {
        const int r = d - HD;
        const int jj = r >> 1;
        const float2 cs = g_trig[h * 32 + jj];
        const long long base = (long long)s * rope_ld + h * RD + 2 * jj;
        const float x1 = rope[base];
        const float x2 = rope[base + 1];
        val = (r & 1) ? (x1 * cs.y + x2 * cs.x) : (x1 * cs.x - x2 * cs.y);
    }
    out[idx] = __uint_as_float(f2tf32(val * mult));
}

// ---------------------------------------------------------------------------
// V transpose (emits tf32 bits)
// ---------------------------------------------------------------------------
__global__ void transpose_kernel(const float* __restrict__ V, int src_ld,
                                 float* __restrict__ VT)
{
    __shared__ float tbuf[32][33];
    const int bx = blockIdx.x * 32;
    const int by = blockIdx.y * 32;
    const int x = threadIdx.x, y = threadIdx.y;
    #pragma unroll
    for (int i = 0; i < 32; i += 8)
        tbuf[y + i][x] = V[(long long)(by + y + i) * src_ld + bx + x];
    __syncthreads();
    #pragma unroll
    for (int i = 0; i < 32; i += 8)
        VT[(long long)(bx + y + i) * S_LEN + by + x] =
            __uint_as_float(f2tf32(tbuf[x][y + i]));
}

// ---------------------------------------------------------------------------
// Host-side launch helpers
// ---------------------------------------------------------------------------
static void gemm_seg(float* C, const float* A, int M, int K, int lda, int Ntot,
                     int cvt_out,
                     const float* B0, const float* bias0,
                     const float* B1 = nullptr, const float* bias1 = nullptr, int n1 = 1 << 30,
                     const float* B2 = nullptr, const float* bias2 = nullptr, int n2 = 1 << 30)
{
    dim3 grid(Ntot / 128, M / 128);
    mma_nt_kernel<<<grid, 256, SMEM_BYTES>>>(A, B0, B1, B2, bias0, bias1, bias2,
                                             n1, n2, C, K, lda, Ntot, cvt_out);
}

static void cvt_buf(float* dst, const float* src, int n)
{
    const int n4 = n / 4;
    cvt_tf32_kernel<<<(n4 + 255) / 256, 256>>>((const float4*)src, (float4*)dst, n4);
}

extern "C" void kernel_launch(void* const* d_in, const int* in_sizes, int n_in,
                              void* d_out, int out_size)
{
    const float* x            = (const float*)d_in[0];
    const float* kv_down_w    = (const float*)d_in[1];
    const float* kv_down_b    = (const float*)d_in[2];
    const float* key_up_w     = (const float*)d_in[3];
    const float* key_up_b     = (const float*)d_in[4];
    const float* value_up_w   = (const float*)d_in[5];
    const float* value_up_b   = (const float*)d_in[6];
    const float* key_rope_w   = (const float*)d_in[7];
    const float* key_rope_b   = (const float*)d_in[8];
    const float* query_down_w = (const float*)d_in[9];
    const float* query_down_b = (const float*)d_in[10];
    const float* query_up_w   = (const float*)d_in[11];
    const float* query_up_b   = (const float*)d_in[12];
    const float* query_rope_w = (const float*)d_in[13];
    const float* query_rope_b = (const float*)d_in[14];
    const float* out_w        = (const float*)d_in[15];
    const float* out_b        = (const float*)d_in[16];
    float* out = (float*)d_out;

    cudaFuncSetAttribute(mma_nt_kernel,
                         cudaFuncAttributeMaxDynamicSharedMemorySize, SMEM_BYTES);
    cudaFuncSetAttribute(flash_kernel,
                         cudaFuncAttributeMaxDynamicSharedMemorySize, FL_SMEM_BYTES);

    float *dq, *kvu, *qu, *Kb, *Qb, *VT, *ctx, *wcv;
    cudaGetSymbolAddress((void**)&dq,  g_dq);
    cudaGetSymbolAddress((void**)&kvu, g_kvu);
    cudaGetSymbolAddress((void**)&qu,  g_qu);
    cudaGetSymbolAddress((void**)&Kb,  g_Kb);
    cudaGetSymbolAddress((void**)&Qb,  g_Qb);
    cudaGetSymbolAddress((void**)&VT,  g_VT);
    cudaGetSymbolAddress((void**)&ctx, g_ctx);
    cudaGetSymbolAddress((void**)&wcv, g_wcv);

    // Converted-operand layout inside g_wcv
    float* xc   = wcv;                 // 2048*2048
    float* kdw  = xc   + 4194304;      // 512*2048
    float* qdw  = kdw  + 1048576;      // 1024*2048
    float* kuw  = qdw  + 2097152;      // 2048*512
    float* vuw  = kuw  + 1048576;      // 2048*512
    float* krw  = vuw  + 1048576;      // 1024*512
    float* quw  = krw  + 524288;       // 2048*1024
    float* qrw  = quw  + 2097152;      // 1024*1024
    float* owc  = qrw  + 1048576;      // 2048*2048

    cvt_buf(xc,  x,            4194304);
    cvt_buf(kdw, kv_down_w,    1048576);
    cvt_buf(qdw, query_down_w, 2097152);
    cvt_buf(kuw, key_up_w,     1048576);
    cvt_buf(vuw, value_up_w,   1048576);
    cvt_buf(krw, key_rope_w,    524288);
    cvt_buf(quw, query_up_w,   2097152);
    cvt_buf(qrw, query_rope_w, 1048576);
    cvt_buf(owc, out_w,        4194304);
    trig_init_kernel<<<1, 512>>>();

    const int DQT = KVC + QCDIM;            // 1536
    const int KVU = 2 * NH * HD + NH * RD;  // 5120
    const int QUT = NH * HD + NH * RD;      // 3072
    const float scale = 1.f / sqrtf((float)DQK);

    // 1. merged down projections: dq = [kvc | qc]  (tf32 out)
    gemm_seg(dq, xc, S_LEN, HIDDEN, HIDDEN, DQT, 1,
             kdw, kv_down_b, qdw, query_down_b, KVC);

    // 2. merged KV up projections: kvu = [kc | V | kr]  (tf32 out)
    gemm_seg(kvu, dq, S_LEN, KVC, DQT, KVU, 1,
             kuw, key_up_b, vuw, value_up_b, NH * HD,
             krw, key_rope_b, 2 * NH * HD);

    // 3. merged Q up projections: qu = [qcu | qr]  (tf32 out)
    gemm_seg(qu, dq + KVC, S_LEN, QCDIM, DQT, QUT, 1,
             quw, query_up_b, qrw, query_rope_b, NH * HD);

    // 4. rope + concat (tf32, Q pre-scaled); V transpose (tf32)
    {
        const int total = S_LEN * NH * DQK;
        const int nb = (total + 255) / 256;
        assemble_rope_kernel<<<nb, 256>>>(kvu, KVU, kvu + 2 * NH * HD, KVU, Kb, 1.f);
        assemble_rope_kernel<<<nb, 256>>>(qu, QUT, qu + NH * HD, QUT, Qb, scale);
        transpose_kernel<<<dim3(64, 64), dim3(32, 8)>>>(kvu + NH * HD, KVU, VT);
    }

    // 5. fused flash attention -> ctx (tf32 out)
    flash_kernel<<<dim3(S_LEN / 128, NH), 512, FL_SMEM_BYTES>>>(Qb, Kb, VT, ctx);

    // 6. output projection (fp32 out)
    gemm_seg(out, ctx, S_LEN, NH * HD, NH * HD, HIDDEN, 0, owc, out_b);
}